// round 9
// baseline (speedup 1.0000x reference)
#include <cuda_runtime.h>
#include <cuda_fp16.h>
#include <cstdint>

#define THETA 0.7f
#define NB   32
#define NC   128
#define NH   128
#define NW   128
#define HWSZ (NH * NW)
#define IMG  (NC * HWSZ)

// ---------------- scratch (static device memory; no allocation) -------------
// xTp: [b][hp=h+1 (0..129)][cc(2)] 16KB blocks, each [128 w][64 ci] fp16,
// SW128 swizzle baked into the byte layout.
static __device__ __align__(1024) unsigned char g_xTp[(size_t)32 * 130 * 2 * 16384];
// Wp: 18 blocks ordered [cc(2)][kh(3)][kw(3)], each 16KB [128 co][64 ci] fp16.
static __device__ __align__(1024) unsigned char g_Wp[18 * 16384];
static __device__ float g_sp[2][NB * HWSZ];   // partial channel sums
static __device__ float g_d[NB * HWSZ];       // THETA * stencil

// ---------------- PTX helpers ----------------------------------------------
__device__ __forceinline__ uint32_t smem_u32(const void* p) {
    uint32_t a;
    asm("{ .reg .u64 t; cvta.to.shared.u64 t, %1; cvt.u32.u64 %0, t; }" : "=r"(a) : "l"(p));
    return a;
}
#define MBAR_INIT(a, n) asm volatile("mbarrier.init.shared.b64 [%0], %1;" :: "r"(a), "r"(n) : "memory")
#define MBAR_EXPECT_TX(a, b) asm volatile("mbarrier.arrive.expect_tx.shared.b64 _, [%0], %1;" :: "r"(a), "r"(b) : "memory")
__device__ __forceinline__ void mbar_wait(uint32_t mbar, uint32_t parity) {
    asm volatile(
        "{\n\t.reg .pred P;\n\t"
        "W_%=:\n\t"
        "mbarrier.try_wait.parity.acquire.cta.shared::cta.b64 P, [%0], %1, 0x989680;\n\t"
        "@!P bra W_%=;\n\t}" :: "r"(mbar), "r"(parity) : "memory");
}
__device__ __forceinline__ void bulk_g2s(uint32_t dst, const void* src, uint32_t bytes, uint32_t mbar) {
    asm volatile(
        "cp.async.bulk.shared::cta.global.mbarrier::complete_tx::bytes [%0], [%1], %2, [%3];"
        :: "r"(dst), "l"(src), "r"(bytes), "r"(mbar) : "memory");
}
__device__ __forceinline__ void ldsm4(uint32_t* r, uint32_t addr) {
    asm volatile("ldmatrix.sync.aligned.m8n8.x4.shared.b16 {%0,%1,%2,%3}, [%4];"
                 : "=r"(r[0]), "=r"(r[1]), "=r"(r[2]), "=r"(r[3]) : "r"(addr));
}
__device__ __forceinline__ void mma16816(float* c, const uint32_t* a, const uint32_t* b) {
    asm volatile(
        "mma.sync.aligned.m16n8k16.row.col.f32.f16.f16.f32 "
        "{%0,%1,%2,%3}, {%4,%5,%6,%7}, {%8,%9}, {%0,%1,%2,%3};"
        : "+f"(c[0]), "+f"(c[1]), "+f"(c[2]), "+f"(c[3])
        : "r"(a[0]), "r"(a[1]), "r"(a[2]), "r"(a[3]), "r"(b[0]), "r"(b[1]));
}
__device__ __forceinline__ uint32_t swz(uint32_t x) { return x ^ ((x >> 3) & 0x70); }

// ---------------- pre-pass kernels ------------------------------------------
__global__ void k_stencil() {
    int idx = blockIdx.x * blockDim.x + threadIdx.x;
    int b = idx >> 14, hw = idx & (HWSZ - 1);
    int h = hw >> 7, w = hw & 127;
    int base = b << 14;
    int hu = (h > 0   ? h - 1 : 0  ), hd = (h < 127 ? h + 1 : 127);
    int wl = (w > 0   ? w - 1 : 0  ), wr = (w < 127 ? w + 1 : 127);
    float c  = g_sp[0][base + hw]            + g_sp[1][base + hw];
    float up = g_sp[0][base + (hu << 7) + w] + g_sp[1][base + (hu << 7) + w];
    float dn = g_sp[0][base + (hd << 7) + w] + g_sp[1][base + (hd << 7) + w];
    float lf = g_sp[0][base + (h << 7) + wl] + g_sp[1][base + (h << 7) + wl];
    float rt = g_sp[0][base + (h << 7) + wr] + g_sp[1][base + (h << 7) + wr];
    g_d[idx] = THETA * (up + dn + lf + rt - 4.f * c);
}

// zero the pad rows hp=0 and hp=129 (2 blocks = 32KB per pad row per b)
__global__ void k_zero() {
    int i = blockIdx.x * blockDim.x + threadIdx.x;   // 131072 float4s total
    int b = i >> 12, rem = i & 4095;
    int pr = rem >> 11, j = rem & 2047;
    size_t off = ((size_t)(b * 130 + (pr ? 129 : 0))) * 32768 + (size_t)j * 16;
    *(float4*)(g_xTp + off) = make_float4(0.f, 0.f, 0.f, 0.f);
}

// weights: fp16 + SW128-bake; block index ((cc*3+kh)*3+kw)
__global__ void k_prep_w(const float* __restrict__ W) {
    int cc = blockIdx.x, kh = blockIdx.y, kw = blockIdx.z;
    size_t base = (size_t)((cc * 3 + kh) * 3 + kw) * 16384;
    for (int i = threadIdx.x; i < 8192; i += 256) {
        int co = i >> 6, ci = i & 63;
        float v = W[((size_t)co * 128 + cc * 64 + ci) * 9 + kh * 3 + kw];
        uint32_t sw = swz((uint32_t)co * 128 + ci * 2);
        *(unsigned short*)(g_Wp + base + sw) = __half_as_ushort(__float2half(v));
    }
}

// x: transpose [ci][w] -> [w][ci], fp16, bake swizzle, + partial chansum
__global__ void k_prep_x(const float* __restrict__ x) {
    extern __shared__ char ps[];
    float* xin = (float*)ps;                                  // [64][129]
    unsigned short* oh = (unsigned short*)(ps + 33024);       // 16KB
    int cc = blockIdx.x, h = blockIdx.y, b = blockIdx.z;
    const float* src = x + (size_t)b * IMG + ((size_t)cc * 64) * 16384 + (size_t)h * 128;
    for (int i = threadIdx.x; i < 8192; i += 256) {
        int ci = i >> 7, w = i & 127;
        xin[ci * 129 + w] = src[(size_t)ci * 16384 + w];
    }
    __syncthreads();
    if (threadIdx.x < 128) {
        int w = threadIdx.x;
        float s = 0.f;
#pragma unroll 16
        for (int ci = 0; ci < 64; ++ci) s += xin[ci * 129 + w];
        g_sp[cc][((size_t)b << 14) + ((size_t)h << 7) + w] = s;
    }
    for (int i = threadIdx.x; i < 8192; i += 256) {
        int w = i >> 6, ci = i & 63;
        uint32_t sw = swz((uint32_t)w * 128 + ci * 2);
        oh[sw >> 1] = __half_as_ushort(__float2half(xin[ci * 129 + w]));
    }
    __syncthreads();
    unsigned char* dst = g_xTp + ((size_t)((b * 130 + h + 1) * 2 + cc)) * 16384;
    float4* d0 = (float4*)dst;
    const float4* s0 = (const float4*)oh;
    for (int i = threadIdx.x; i < 1024; i += 256) d0[i] = s0[i];
}

// ---------------- main mma.sync kernel ---------------------------------------
// CTA = 2 output rows (h0, h0+1) x 128 co x 128 w; 256 threads, 8 warps.
// warp: p = wid&1 (row), n_g = (wid>>1)&1 (64w half), co_g = wid>>2 (64co half)
// Warp tile: 64 co x 64 w -> C[32][4] = 128 regs.
// SMEM: [8] xbar, [16],[24] wbar0/1; [256..384) zero row;
//       X: 1024 + 8*16384 = 131072  ([d(4)][cc(2)] blocks, resident)
//       W: 132096 + 2*49152 (double-buffered 3-kw chunk) -> total 230400
// X region reused as outs[128][132] in the epilogue.
#define X_OFF 1024u
#define W_OFF 132096u
#define SMEM_TOTAL 230400

__global__ void __launch_bounds__(256, 1) k_main(const float* __restrict__ bias,
                                                 float* __restrict__ out) {
    extern __shared__ __align__(1024) char smem[];
    uint32_t sb = smem_u32(smem);
    const int tid = threadIdx.x, wid = tid >> 5, lane = tid & 31;
    const int p    = wid & 1;
    const int n_g  = (wid >> 1) & 1;
    const int co_g = wid >> 2;            // 0..1
    const int h0 = blockIdx.x * 2, b = blockIdx.y;
    const unsigned char* xp = g_xTp + (size_t)b * 130 * 32768;
    const uint32_t zaddr = sb + 256;

    if (tid == 0) { MBAR_INIT(sb + 8, 1); MBAR_INIT(sb + 16, 1); MBAR_INIT(sb + 24, 1); }
    if (tid < 32) ((float*)(smem + 256))[tid] = 0.f;

    // prologue: 8 X blocks (rows h0-1..h0+2 x 2 cc), W stages 0 and 1 (48KB each)
    if (tid == 0) {
        MBAR_EXPECT_TX(sb + 8, 131072u);
#pragma unroll
        for (int d = 0; d < 4; ++d)
#pragma unroll
            for (int cc = 0; cc < 2; ++cc)
                bulk_g2s(sb + X_OFF + (uint32_t)(d * 2 + cc) * 16384u,
                         xp + (size_t)((h0 + d) * 2 + cc) * 16384, 16384u, sb + 8);
        MBAR_EXPECT_TX(sb + 16, 49152u);
        bulk_g2s(sb + W_OFF, g_Wp, 49152u, sb + 16);
        MBAR_EXPECT_TX(sb + 24, 49152u);
        bulk_g2s(sb + W_OFF + 49152u, g_Wp + 49152, 49152u, sb + 24);
    }
    __syncthreads();   // zero-row + mbar init visible

    // ldmatrix per-thread coordinates (verified mapping)
    const int a_row = co_g * 64 + ((lane & 7) | (((lane >> 3) & 1) << 3));
    const uint32_t a_kb = (uint32_t)((lane >> 4) << 4);
    const int b_n  = (lane & 7) + ((lane >> 4) << 3) + n_g * 64;
    const uint32_t b_kb = (uint32_t)(((lane >> 3) & 1) << 4);
    const uint32_t a_xor = (uint32_t)((a_row & 7) << 4);

    float C[32][4];   // [mt(4) x nt(8)][4]
#pragma unroll
    for (int t = 0; t < 32; ++t)
#pragma unroll
        for (int i = 0; i < 4; ++i) C[t][i] = 0.f;

    for (int s = 0; s < 6; ++s) {
        const int cc = s / 3, kh = s % 3;

        if (s == 0) mbar_wait(sb + 8, 0);
        mbar_wait(sb + 16u + (uint32_t)((s & 1) << 3), (uint32_t)(s >> 1) & 1u);

        const uint32_t wbuf = sb + W_OFF + (uint32_t)((s & 1) ? 49152u : 0u);
        const uint32_t xb = sb + X_OFF + (uint32_t)((p + kh) * 2 + cc) * 16384u;

#pragma unroll
        for (int kw = 0; kw < 3; ++kw) {
            const uint32_t wkw = wbuf + (uint32_t)kw * 16384u
                               + (uint32_t)a_row * 128u;
            // B row bases (kw folded as +-1 row shift; OOB -> zero row)
            uint32_t rh[4], rx[4];
#pragma unroll
            for (int ntp = 0; ntp < 4; ++ntp) {
                int r = b_n + ntp * 16 + kw - 1;
                if ((unsigned)r > 127u) { rh[ntp] = zaddr; rx[ntp] = 0u; }
                else { rh[ntp] = xb + (uint32_t)r * 128u; rx[ntp] = (uint32_t)((r & 7) << 4); }
            }
#pragma unroll
            for (int ks = 0; ks < 4; ++ks) {
                const uint32_t koA = ((uint32_t)(ks * 32) + a_kb) ^ a_xor;
                const uint32_t koB = (uint32_t)(ks * 32) + b_kb;
                uint32_t ah[16], bh[16];
#pragma unroll
                for (int mt = 0; mt < 4; ++mt)
                    ldsm4(&ah[mt * 4], wkw + (uint32_t)(mt * 2048) + koA);
#pragma unroll
                for (int ntp = 0; ntp < 4; ++ntp)
                    ldsm4(&bh[ntp * 4], rh[ntp] + (koB ^ rx[ntp]));
#pragma unroll
                for (int mt = 0; mt < 4; ++mt)
#pragma unroll
                    for (int nt = 0; nt < 8; ++nt)
                        mma16816(C[mt * 8 + nt], &ah[mt * 4],
                                 &bh[((nt >> 1) << 2) + ((nt & 1) << 1)]);
            }
        }

        __syncthreads();   // W buffer s fully consumed before refill
        if (tid == 0 && s + 2 < 6) {
            uint32_t mb = sb + 16u + (uint32_t)((s & 1) << 3);
            MBAR_EXPECT_TX(mb, 49152u);
            bulk_g2s(sb + W_OFF + (uint32_t)((s & 1) ? 49152u : 0u),
                     g_Wp + (size_t)(s + 2) * 49152, 49152u, mb);
        }
    }

    // ---- epilogue: per row, stage C into SMEM (reuse X region), write out ----
    float* outs = (float*)(smem + X_OFF);   // [128 co][132]
    const int row0 = co_g * 64 + (lane >> 2);
    const int col0 = n_g * 64 + 2 * (lane & 3);
#pragma unroll
    for (int pp = 0; pp < 2; ++pp) {
        if (p == pp) {
#pragma unroll
            for (int mt = 0; mt < 4; ++mt)
#pragma unroll
                for (int nt = 0; nt < 8; ++nt) {
                    int rr = row0 + mt * 16;
                    int c = col0 + nt * 8;
                    float* Cp = C[mt * 8 + nt];
                    *(float2*)&outs[rr * 132 + c]       = make_float2(Cp[0], Cp[1]);
                    *(float2*)&outs[(rr + 8) * 132 + c] = make_float2(Cp[2], Cp[3]);
                }
        }
        __syncthreads();
        const float* gd = g_d + ((size_t)b << 14) + ((size_t)(h0 + pp) << 7);
        for (int i = tid; i < 4096; i += 256) {
            int co = i >> 5, w4 = (i & 31) << 2;
            float4 v = *(const float4*)&outs[co * 132 + w4];
            float4 g = *(const float4*)&gd[w4];
            float bv = __ldg(&bias[co]);
            v.x += bv - g.x; v.y += bv - g.y; v.z += bv - g.z; v.w += bv - g.w;
            *(float4*)&out[(size_t)b * IMG + ((size_t)co << 14)
                           + ((size_t)(h0 + pp) << 7) + w4] = v;
        }
        __syncthreads();
    }
}

// ---------------------------------------------------------------------------
extern "C" void kernel_launch(void* const* d_in, const int* in_sizes, int n_in,
                              void* d_out, int out_size) {
    const float* x  = (const float*)d_in[0];
    const float* Wt = (const float*)d_in[1];
    const float* bb = (const float*)d_in[2];
    float* out = (float*)d_out;
    (void)in_sizes; (void)n_in; (void)out_size;

    cudaFuncSetAttribute(k_prep_x, cudaFuncAttributeMaxDynamicSharedMemorySize, 49408);
    cudaFuncSetAttribute(k_main,   cudaFuncAttributeMaxDynamicSharedMemorySize, SMEM_TOTAL);

    k_prep_w<<<dim3(2, 3, 3), 256>>>(Wt);
    k_zero<<<512, 256>>>();
    k_prep_x<<<dim3(2, 128, 32), 256, 49408>>>(x);
    k_stencil<<<NB * HWSZ / 256, 256>>>();
    k_main<<<dim3(64, 32), 256, SMEM_TOTAL>>>(bb, out);
}

// round 10
// speedup vs baseline: 1.0766x; 1.0766x over previous
#include <cuda_runtime.h>
#include <cuda_fp16.h>
#include <cstdint>

#define THETA 0.7f
#define NB   32
#define NC   128
#define NH   128
#define NW   128
#define HWSZ (NH * NW)
#define IMG  (NC * HWSZ)

// ---------------- scratch (static device memory; no allocation) -------------
// xTp: [b][hp=h+1 (0..129)][cc(2)] 16KB blocks, each [128 w][64 ci] fp16,
// SW128 swizzle baked into the byte layout.
static __device__ __align__(1024) unsigned char g_xTp[(size_t)32 * 130 * 2 * 16384];
// Wp: 18 blocks ordered [cc(2)][kh(3)][kw(3)], each 16KB [128 co][64 ci] fp16.
static __device__ __align__(1024) unsigned char g_Wp[18 * 16384];
static __device__ float g_sp[2][NB * HWSZ];   // partial channel sums
static __device__ float g_d[NB * HWSZ];       // THETA * stencil

// ---------------- PTX helpers ----------------------------------------------
__device__ __forceinline__ uint32_t smem_u32(const void* p) {
    uint32_t a;
    asm("{ .reg .u64 t; cvta.to.shared.u64 t, %1; cvt.u32.u64 %0, t; }" : "=r"(a) : "l"(p));
    return a;
}
#define MBAR_INIT(a, n) asm volatile("mbarrier.init.shared.b64 [%0], %1;" :: "r"(a), "r"(n) : "memory")
#define MBAR_EXPECT_TX(a, b) asm volatile("mbarrier.arrive.expect_tx.shared.b64 _, [%0], %1;" :: "r"(a), "r"(b) : "memory")
__device__ __forceinline__ void mbar_wait(uint32_t mbar, uint32_t parity) {
    asm volatile(
        "{\n\t.reg .pred P;\n\t"
        "W_%=:\n\t"
        "mbarrier.try_wait.parity.acquire.cta.shared::cta.b64 P, [%0], %1, 0x989680;\n\t"
        "@!P bra W_%=;\n\t}" :: "r"(mbar), "r"(parity) : "memory");
}
__device__ __forceinline__ void bulk_g2s(uint32_t dst, const void* src, uint32_t bytes, uint32_t mbar) {
    asm volatile(
        "cp.async.bulk.shared::cta.global.mbarrier::complete_tx::bytes [%0], [%1], %2, [%3];"
        :: "r"(dst), "l"(src), "r"(bytes), "r"(mbar) : "memory");
}
__device__ __forceinline__ void ldsm4(uint32_t* r, uint32_t addr) {
    asm volatile("ldmatrix.sync.aligned.m8n8.x4.shared.b16 {%0,%1,%2,%3}, [%4];"
                 : "=r"(r[0]), "=r"(r[1]), "=r"(r[2]), "=r"(r[3]) : "r"(addr));
}
__device__ __forceinline__ void mma16816(float* c, const uint32_t* a, const uint32_t* b) {
    asm volatile(
        "mma.sync.aligned.m16n8k16.row.col.f32.f16.f16.f32 "
        "{%0,%1,%2,%3}, {%4,%5,%6,%7}, {%8,%9}, {%0,%1,%2,%3};"
        : "+f"(c[0]), "+f"(c[1]), "+f"(c[2]), "+f"(c[3])
        : "r"(a[0]), "r"(a[1]), "r"(a[2]), "r"(a[3]), "r"(b[0]), "r"(b[1]));
}
__device__ __forceinline__ uint32_t swz(uint32_t x) { return x ^ ((x >> 3) & 0x70); }

// ---------------- pre-pass kernels ------------------------------------------
__global__ void k_stencil() {
    int idx = blockIdx.x * blockDim.x + threadIdx.x;
    int b = idx >> 14, hw = idx & (HWSZ - 1);
    int h = hw >> 7, w = hw & 127;
    int base = b << 14;
    int hu = (h > 0   ? h - 1 : 0  ), hd = (h < 127 ? h + 1 : 127);
    int wl = (w > 0   ? w - 1 : 0  ), wr = (w < 127 ? w + 1 : 127);
    float c  = g_sp[0][base + hw]            + g_sp[1][base + hw];
    float up = g_sp[0][base + (hu << 7) + w] + g_sp[1][base + (hu << 7) + w];
    float dn = g_sp[0][base + (hd << 7) + w] + g_sp[1][base + (hd << 7) + w];
    float lf = g_sp[0][base + (h << 7) + wl] + g_sp[1][base + (h << 7) + wl];
    float rt = g_sp[0][base + (h << 7) + wr] + g_sp[1][base + (h << 7) + wr];
    g_d[idx] = THETA * (up + dn + lf + rt - 4.f * c);
}

// zero the pad rows hp=0 and hp=129 (2 blocks = 32KB per pad row per b)
__global__ void k_zero() {
    int i = blockIdx.x * blockDim.x + threadIdx.x;   // 131072 float4s total
    int b = i >> 12, rem = i & 4095;
    int pr = rem >> 11, j = rem & 2047;
    size_t off = ((size_t)(b * 130 + (pr ? 129 : 0))) * 32768 + (size_t)j * 16;
    *(float4*)(g_xTp + off) = make_float4(0.f, 0.f, 0.f, 0.f);
}

// weights: fp16 + SW128-bake; block index ((cc*3+kh)*3+kw)
__global__ void k_prep_w(const float* __restrict__ W) {
    int cc = blockIdx.x, kh = blockIdx.y, kw = blockIdx.z;
    size_t base = (size_t)((cc * 3 + kh) * 3 + kw) * 16384;
    for (int i = threadIdx.x; i < 8192; i += 256) {
        int co = i >> 6, ci = i & 63;
        float v = W[((size_t)co * 128 + cc * 64 + ci) * 9 + kh * 3 + kw];
        uint32_t sw = swz((uint32_t)co * 128 + ci * 2);
        *(unsigned short*)(g_Wp + base + sw) = __half_as_ushort(__float2half(v));
    }
}

// x: transpose [ci][w] -> [w][ci], fp16, bake swizzle, + partial chansum
__global__ void k_prep_x(const float* __restrict__ x) {
    extern __shared__ char ps[];
    float* xin = (float*)ps;                                  // [64][129]
    unsigned short* oh = (unsigned short*)(ps + 33024);       // 16KB
    int cc = blockIdx.x, h = blockIdx.y, b = blockIdx.z;
    const float* src = x + (size_t)b * IMG + ((size_t)cc * 64) * 16384 + (size_t)h * 128;
    for (int i = threadIdx.x; i < 8192; i += 256) {
        int ci = i >> 7, w = i & 127;
        xin[ci * 129 + w] = src[(size_t)ci * 16384 + w];
    }
    __syncthreads();
    if (threadIdx.x < 128) {
        int w = threadIdx.x;
        float s = 0.f;
#pragma unroll 16
        for (int ci = 0; ci < 64; ++ci) s += xin[ci * 129 + w];
        g_sp[cc][((size_t)b << 14) + ((size_t)h << 7) + w] = s;
    }
    for (int i = threadIdx.x; i < 8192; i += 256) {
        int w = i >> 6, ci = i & 63;
        uint32_t sw = swz((uint32_t)w * 128 + ci * 2);
        oh[sw >> 1] = __half_as_ushort(__float2half(xin[ci * 129 + w]));
    }
    __syncthreads();
    unsigned char* dst = g_xTp + ((size_t)((b * 130 + h + 1) * 2 + cc)) * 16384;
    float4* d0 = (float4*)dst;
    const float4* s0 = (const float4*)oh;
    for (int i = threadIdx.x; i < 1024; i += 256) d0[i] = s0[i];
}

// ---------------- main mma.sync kernel ---------------------------------------
// CTA = 2 output rows (h0, h0+1) x 128 co x 128 w; 512 threads, 16 warps.
// warp: p = wid&1 (row), n_g = (wid>>1)&1 (64w half), co_g = wid>>2 (32co group)
// SMEM: [8] xbar0, [16] xbar1, [24],[32] wbar0/1; [64..192) zero row;
//       [256..1280) gd rows (2x128 f32);
//       X: 2048 + 8*16384 = 133120  ([d(4)][cc(2)] blocks, resident)
//       W: 133120 + 2*49152         -> total 231424
#define X_OFF 2048u
#define W_OFF 133120u
#define SMEM_TOTAL 231424

__global__ void __launch_bounds__(512, 1) k_main(const float* __restrict__ bias,
                                                 float* __restrict__ out) {
    extern __shared__ __align__(1024) char smem[];
    uint32_t sb = smem_u32(smem);
    const int tid = threadIdx.x, wid = tid >> 5, lane = tid & 31;
    const int p    = wid & 1;
    const int n_g  = (wid >> 1) & 1;
    const int co_g = wid >> 2;            // 0..3
    const int h0 = blockIdx.x * 2, b = blockIdx.y;
    const unsigned char* xp = g_xTp + (size_t)b * 130 * 32768;
    const uint32_t zaddr = sb + 64;

    if (tid == 0) {
        MBAR_INIT(sb + 8, 1);  MBAR_INIT(sb + 16, 1);
        MBAR_INIT(sb + 24, 1); MBAR_INIT(sb + 32, 1);
    }
    if (tid < 32) ((float*)(smem + 64))[tid] = 0.f;
    // stage g_d rows for the epilogue (2 x 128 floats)
    float* smg = (float*)(smem + 256);
    if (tid < 256)
        smg[tid] = g_d[((size_t)b << 14) + ((size_t)(h0 + (tid >> 7)) << 7) + (tid & 127)];

    // prologue: X blocks split across 2 barriers; W stages 0 and 1 (48KB each)
    if (tid == 0) {
        // xbar0: rows h0-1, h0 of cc0 (all that stage 0 needs)
        MBAR_EXPECT_TX(sb + 8, 32768u);
        bulk_g2s(sb + X_OFF,              xp + (size_t)((h0 + 0) * 2 + 0) * 16384, 16384u, sb + 8);
        bulk_g2s(sb + X_OFF + 2u * 16384u, xp + (size_t)((h0 + 1) * 2 + 0) * 16384, 16384u, sb + 8);
        // xbar1: the remaining 6 blocks
        MBAR_EXPECT_TX(sb + 16, 98304u);
        bulk_g2s(sb + X_OFF + 1u * 16384u, xp + (size_t)((h0 + 0) * 2 + 1) * 16384, 16384u, sb + 16);
        bulk_g2s(sb + X_OFF + 3u * 16384u, xp + (size_t)((h0 + 1) * 2 + 1) * 16384, 16384u, sb + 16);
#pragma unroll
        for (int d = 2; d < 4; ++d)
#pragma unroll
            for (int cc = 0; cc < 2; ++cc)
                bulk_g2s(sb + X_OFF + (uint32_t)(d * 2 + cc) * 16384u,
                         xp + (size_t)((h0 + d) * 2 + cc) * 16384, 16384u, sb + 16);
        MBAR_EXPECT_TX(sb + 24, 49152u);
        bulk_g2s(sb + W_OFF, g_Wp, 49152u, sb + 24);
        MBAR_EXPECT_TX(sb + 32, 49152u);
        bulk_g2s(sb + W_OFF + 49152u, g_Wp + 49152, 49152u, sb + 32);
    }
    __syncthreads();   // zero-row + gd + mbar init visible

    // ldmatrix per-thread coordinates (verified mapping)
    const int a_row = co_g * 32 + ((lane & 7) | (((lane >> 3) & 1) << 3));
    const uint32_t a_kb = (uint32_t)((lane >> 4) << 4);
    const int b_n  = (lane & 7) + ((lane >> 4) << 3) + n_g * 64;
    const uint32_t b_kb = (uint32_t)(((lane >> 3) & 1) << 4);
    const uint32_t a_xor = (uint32_t)((a_row & 7) << 4);

    float C[16][4];   // [s16(2) x nt(8)][4]
#pragma unroll
    for (int nt = 0; nt < 16; ++nt)
#pragma unroll
        for (int i = 0; i < 4; ++i) C[nt][i] = 0.f;

    for (int s = 0; s < 6; ++s) {
        const int cc = s / 3, kh = s % 3;

        if (s == 0) mbar_wait(sb + 8, 0);
        if (s == 1) mbar_wait(sb + 16, 0);
        mbar_wait(sb + 24u + (uint32_t)((s & 1) << 3), (uint32_t)(s >> 1) & 1u);

        const uint32_t wbuf = sb + W_OFF + (uint32_t)((s & 1) ? 49152u : 0u);
        const uint32_t xb = sb + X_OFF + (uint32_t)((p + kh) * 2 + cc) * 16384u;

#pragma unroll
        for (int kw = 0; kw < 3; ++kw) {
            const uint32_t wkw = wbuf + (uint32_t)kw * 16384u
                               + (uint32_t)a_row * 128u;
            // B row bases (kw folded as +-1 row shift; OOB -> zero row)
            uint32_t rh[4], rx[4];
#pragma unroll
            for (int ntp = 0; ntp < 4; ++ntp) {
                int r = b_n + ntp * 16 + kw - 1;
                if ((unsigned)r > 127u) { rh[ntp] = zaddr; rx[ntp] = 0u; }
                else { rh[ntp] = xb + (uint32_t)r * 128u; rx[ntp] = (uint32_t)((r & 7) << 4); }
            }
#pragma unroll
            for (int ks = 0; ks < 4; ++ks) {
                const uint32_t koA = (uint32_t)(ks * 32) + a_kb;
                const uint32_t koB = (uint32_t)(ks * 32) + b_kb;
                uint32_t ah0[4], ah1[4], bh[16];
                ldsm4(ah0, wkw + (koA ^ a_xor));
                ldsm4(ah1, wkw + 2048u + (koA ^ a_xor));   // +16 rows * 128B
#pragma unroll
                for (int ntp = 0; ntp < 4; ++ntp)
                    ldsm4(&bh[ntp * 4], rh[ntp] + (koB ^ rx[ntp]));
#pragma unroll
                for (int nt = 0; nt < 8; ++nt)
                    mma16816(C[nt], ah0, &bh[((nt >> 1) << 2) + ((nt & 1) << 1)]);
#pragma unroll
                for (int nt = 0; nt < 8; ++nt)
                    mma16816(C[8 + nt], ah1, &bh[((nt >> 1) << 2) + ((nt & 1) << 1)]);
            }
        }

        __syncthreads();   // W buffer s fully consumed before refill
        if (tid == 0 && s + 2 < 6) {
            uint32_t mb = sb + 24u + (uint32_t)((s & 1) << 3);
            MBAR_EXPECT_TX(mb, 49152u);
            bulk_g2s(sb + W_OFF + (uint32_t)((s & 1) ? 49152u : 0u),
                     g_Wp + (size_t)(s + 2) * 49152, 49152u, mb);
        }
    }

    // ---- epilogue: direct register -> gmem, bias & stencil fused ------------
    const int row0 = co_g * 32 + (lane >> 2);
    const int col0 = n_g * 64 + 2 * (lane & 3);
    const float* gdp = smg + p * 128;
    float* ob = out + (size_t)b * IMG + ((size_t)(h0 + p) << 7);
#pragma unroll
    for (int s16 = 0; s16 < 2; ++s16) {
        const int r0 = row0 + s16 * 16;
        const float bv0 = __ldg(&bias[r0]);
        const float bv1 = __ldg(&bias[r0 + 8]);
        float* o0 = ob + ((size_t)r0 << 14);
        float* o1 = ob + ((size_t)(r0 + 8) << 14);
#pragma unroll
        for (int nt = 0; nt < 8; ++nt) {
            const int c = col0 + nt * 8;
            const float g0 = gdp[c], g1 = gdp[c + 1];
            float* Cp = C[s16 * 8 + nt];
            *(float2*)&o0[c] = make_float2(Cp[0] + bv0 - g0, Cp[1] + bv0 - g1);
            *(float2*)&o1[c] = make_float2(Cp[2] + bv1 - g0, Cp[3] + bv1 - g1);
        }
    }
}

// ---------------------------------------------------------------------------
extern "C" void kernel_launch(void* const* d_in, const int* in_sizes, int n_in,
                              void* d_out, int out_size) {
    const float* x  = (const float*)d_in[0];
    const float* Wt = (const float*)d_in[1];
    const float* bb = (const float*)d_in[2];
    float* out = (float*)d_out;
    (void)in_sizes; (void)n_in; (void)out_size;

    cudaFuncSetAttribute(k_prep_x, cudaFuncAttributeMaxDynamicSharedMemorySize, 49408);
    cudaFuncSetAttribute(k_main,   cudaFuncAttributeMaxDynamicSharedMemorySize, SMEM_TOTAL);

    k_prep_w<<<dim3(2, 3, 3), 256>>>(Wt);
    k_zero<<<512, 256>>>();
    k_prep_x<<<dim3(2, 128, 32), 256, 49408>>>(x);
    k_stencil<<<NB * HWSZ / 256, 256>>>();
    k_main<<<dim3(64, 32), 512, SMEM_TOTAL>>>(bb, out);
}

// round 11
// speedup vs baseline: 1.1004x; 1.0220x over previous
#include <cuda_runtime.h>
#include <cuda_fp16.h>
#include <cstdint>

#define THETA 0.7f
#define NB   32
#define NC   128
#define NH   128
#define NW   128
#define HWSZ (NH * NW)
#define IMG  (NC * HWSZ)
#define NTILES 2048
#define NCTA   148

// ---------------- scratch (static device memory; no allocation) -------------
// xTp: [b][hp=h+1 (0..129)][cc(2)] 16KB blocks, each [128 w][64 ci] fp16,
// SW128 swizzle baked into the byte layout.
static __device__ __align__(1024) unsigned char g_xTp[(size_t)32 * 130 * 2 * 16384];
// Wp: 18 blocks ordered [(kh*2+cc)][kw], each 16KB [128 co][64 ci] fp16.
static __device__ __align__(1024) unsigned char g_Wp[18 * 16384];
static __device__ float g_sp[2][NB * HWSZ];   // partial channel sums
static __device__ float g_d[NB * HWSZ];       // THETA * stencil

// ---------------- PTX helpers ----------------------------------------------
__device__ __forceinline__ uint32_t smem_u32(const void* p) {
    uint32_t a;
    asm("{ .reg .u64 t; cvta.to.shared.u64 t, %1; cvt.u32.u64 %0, t; }" : "=r"(a) : "l"(p));
    return a;
}
#define MBAR_INIT(a, n) asm volatile("mbarrier.init.shared.b64 [%0], %1;" :: "r"(a), "r"(n) : "memory")
#define MBAR_EXPECT_TX(a, b) asm volatile("mbarrier.arrive.expect_tx.shared.b64 _, [%0], %1;" :: "r"(a), "r"(b) : "memory")
__device__ __forceinline__ void mbar_wait(uint32_t mbar, uint32_t parity) {
    asm volatile(
        "{\n\t.reg .pred P;\n\t"
        "W_%=:\n\t"
        "mbarrier.try_wait.parity.acquire.cta.shared::cta.b64 P, [%0], %1, 0x989680;\n\t"
        "@!P bra W_%=;\n\t}" :: "r"(mbar), "r"(parity) : "memory");
}
__device__ __forceinline__ void bulk_g2s(uint32_t dst, const void* src, uint32_t bytes, uint32_t mbar) {
    asm volatile(
        "cp.async.bulk.shared::cta.global.mbarrier::complete_tx::bytes [%0], [%1], %2, [%3];"
        :: "r"(dst), "l"(src), "r"(bytes), "r"(mbar) : "memory");
}
__device__ __forceinline__ void ldsm4(uint32_t* r, uint32_t addr) {
    asm volatile("ldmatrix.sync.aligned.m8n8.x4.shared.b16 {%0,%1,%2,%3}, [%4];"
                 : "=r"(r[0]), "=r"(r[1]), "=r"(r[2]), "=r"(r[3]) : "r"(addr));
}
__device__ __forceinline__ void mma16816(float* c, const uint32_t* a, const uint32_t* b) {
    asm volatile(
        "mma.sync.aligned.m16n8k16.row.col.f32.f16.f16.f32 "
        "{%0,%1,%2,%3}, {%4,%5,%6,%7}, {%8,%9}, {%0,%1,%2,%3};"
        : "+f"(c[0]), "+f"(c[1]), "+f"(c[2]), "+f"(c[3])
        : "r"(a[0]), "r"(a[1]), "r"(a[2]), "r"(a[3]), "r"(b[0]), "r"(b[1]));
}
__device__ __forceinline__ uint32_t swz(uint32_t x) { return x ^ ((x >> 3) & 0x70); }

// ---------------- pre-pass kernels ------------------------------------------
__global__ void k_stencil() {
    int idx = blockIdx.x * blockDim.x + threadIdx.x;
    int b = idx >> 14, hw = idx & (HWSZ - 1);
    int h = hw >> 7, w = hw & 127;
    int base = b << 14;
    int hu = (h > 0   ? h - 1 : 0  ), hd = (h < 127 ? h + 1 : 127);
    int wl = (w > 0   ? w - 1 : 0  ), wr = (w < 127 ? w + 1 : 127);
    float c  = g_sp[0][base + hw]            + g_sp[1][base + hw];
    float up = g_sp[0][base + (hu << 7) + w] + g_sp[1][base + (hu << 7) + w];
    float dn = g_sp[0][base + (hd << 7) + w] + g_sp[1][base + (hd << 7) + w];
    float lf = g_sp[0][base + (h << 7) + wl] + g_sp[1][base + (h << 7) + wl];
    float rt = g_sp[0][base + (h << 7) + wr] + g_sp[1][base + (h << 7) + wr];
    g_d[idx] = THETA * (up + dn + lf + rt - 4.f * c);
}

// zero the pad rows hp=0 and hp=129 (2 blocks = 32KB per pad row per b)
__global__ void k_zero() {
    int i = blockIdx.x * blockDim.x + threadIdx.x;   // 131072 float4s total
    int b = i >> 12, rem = i & 4095;
    int pr = rem >> 11, j = rem & 2047;
    size_t off = ((size_t)(b * 130 + (pr ? 129 : 0))) * 32768 + (size_t)j * 16;
    *(float4*)(g_xTp + off) = make_float4(0.f, 0.f, 0.f, 0.f);
}

// weights: fp16 + SW128-bake; block index ((kh*2+cc)*3+kw)
__global__ void k_prep_w(const float* __restrict__ W) {
    int cc = blockIdx.x, kh = blockIdx.y, kw = blockIdx.z;
    size_t base = (size_t)((kh * 2 + cc) * 3 + kw) * 16384;
    for (int i = threadIdx.x; i < 8192; i += 256) {
        int co = i >> 6, ci = i & 63;
        float v = W[((size_t)co * 128 + cc * 64 + ci) * 9 + kh * 3 + kw];
        uint32_t sw = swz((uint32_t)co * 128 + ci * 2);
        *(unsigned short*)(g_Wp + base + sw) = __half_as_ushort(__float2half(v));
    }
}

// x: transpose [ci][w] -> [w][ci], fp16, bake swizzle, + partial chansum
__global__ void k_prep_x(const float* __restrict__ x) {
    extern __shared__ char ps[];
    float* xin = (float*)ps;                                  // [64][129]
    unsigned short* oh = (unsigned short*)(ps + 33024);       // 16KB
    int cc = blockIdx.x, h = blockIdx.y, b = blockIdx.z;
    const float* src = x + (size_t)b * IMG + ((size_t)cc * 64) * 16384 + (size_t)h * 128;
    for (int i = threadIdx.x; i < 8192; i += 256) {
        int ci = i >> 7, w = i & 127;
        xin[ci * 129 + w] = src[(size_t)ci * 16384 + w];
    }
    __syncthreads();
    if (threadIdx.x < 128) {
        int w = threadIdx.x;
        float s = 0.f;
#pragma unroll 16
        for (int ci = 0; ci < 64; ++ci) s += xin[ci * 129 + w];
        g_sp[cc][((size_t)b << 14) + ((size_t)h << 7) + w] = s;
    }
    for (int i = threadIdx.x; i < 8192; i += 256) {
        int w = i >> 6, ci = i & 63;
        uint32_t sw = swz((uint32_t)w * 128 + ci * 2);
        oh[sw >> 1] = __half_as_ushort(__float2half(xin[ci * 129 + w]));
    }
    __syncthreads();
    unsigned char* dst = g_xTp + ((size_t)((b * 130 + h + 1) * 2 + cc)) * 16384;
    float4* d0 = (float4*)dst;
    const float4* s0 = (const float4*)oh;
    for (int i = threadIdx.x; i < 1024; i += 256) d0[i] = s0[i];
}

// ---------------- main persistent mma.sync kernel ----------------------------
// 148 CTAs; CTA i handles tiles [i*2048/148, (i+1)*2048/148).
// Tile = 2 output rows (h0,h0+1) x 128co x 128w. 512 threads, 16 warps.
// warp: p = wid&1 (row), n_g = (wid>>1)&1 (64w half), co_g = wid>>2 (32co group)
// Stage s (0..5): kh = s>>1, cc = s&1. Warp uses x row hp = h0+p+kh,
// slot = hp&3. Rows h0,h0+1 dead after s=3 -> prefetch next tile's 2 rows.
// SMEM: [8] xbar, [24],[32] wbar0/1; [64..192) zero row;
//       X ring: 2048 + 8*16384 = 133120  ([slot(4)][cc(2)] blocks)
//       W: 133120 + 2*49152 -> total 231424
#define X_OFF 2048u
#define W_OFF 133120u
#define SMEM_TOTAL 231424

__global__ void __launch_bounds__(512, 1) k_main(const float* __restrict__ bias,
                                                 float* __restrict__ out) {
    extern __shared__ __align__(1024) char smem[];
    uint32_t sb = smem_u32(smem);
    const int tid = threadIdx.x, wid = tid >> 5, lane = tid & 31;
    const int p    = wid & 1;
    const int n_g  = (wid >> 1) & 1;
    const int co_g = wid >> 2;            // 0..3
    const uint32_t zaddr = sb + 64;

    const int start = (blockIdx.x * NTILES) / NCTA;
    const int end   = ((blockIdx.x + 1) * NTILES) / NCTA;
    const int nstages = 6 * (end - start);

    if (tid == 0) { MBAR_INIT(sb + 8, 1); MBAR_INIT(sb + 24, 1); MBAR_INIT(sb + 32, 1); }
    if (tid < 32) ((float*)(smem + 64))[tid] = 0.f;

    // prologue: X rows hp=h0..h0+3 of first tile, W chunks 0 and 1
    {
        int b0 = start >> 6, h0 = (start & 63) * 2;
        const unsigned char* xp0 = g_xTp + (size_t)b0 * 130 * 32768;
        if (tid == 0) {
            MBAR_EXPECT_TX(sb + 8, 131072u);
#pragma unroll
            for (int d = 0; d < 4; ++d)
#pragma unroll
                for (int cc = 0; cc < 2; ++cc)
                    bulk_g2s(sb + X_OFF + (uint32_t)((((h0 + d) & 3) * 2 + cc)) * 16384u,
                             xp0 + (size_t)((h0 + d) * 2 + cc) * 16384, 16384u, sb + 8);
            MBAR_EXPECT_TX(sb + 24, 49152u);
            bulk_g2s(sb + W_OFF, g_Wp, 49152u, sb + 24);
            MBAR_EXPECT_TX(sb + 32, 49152u);
            bulk_g2s(sb + W_OFF + 49152u, g_Wp + 49152, 49152u, sb + 32);
        }
    }
    __syncthreads();   // zero-row + mbar init visible

    // ldmatrix per-thread coordinates (verified mapping)
    const int a_row = co_g * 32 + ((lane & 7) | (((lane >> 3) & 1) << 3));
    const uint32_t a_kb = (uint32_t)((lane >> 4) << 4);
    const int b_n  = (lane & 7) + ((lane >> 4) << 3) + n_g * 64;
    const uint32_t b_kb = (uint32_t)(((lane >> 3) & 1) << 4);
    const uint32_t a_xor = (uint32_t)((a_row & 7) << 4);

    // epilogue constants
    const int row0 = co_g * 32 + (lane >> 2);
    const int col0 = n_g * 64 + 2 * (lane & 3);
    const float bv00 = __ldg(&bias[row0]),      bv01 = __ldg(&bias[row0 + 8]);
    const float bv10 = __ldg(&bias[row0 + 16]), bv11 = __ldg(&bias[row0 + 24]);

    float C[16][4];
#pragma unroll
    for (int nt = 0; nt < 16; ++nt)
#pragma unroll
        for (int i = 0; i < 4; ++i) C[nt][i] = 0.f;

    int g = 0;        // global W-stage counter
    int xev = 0;      // X arrival events consumed (parity = xev&1)

    for (int t = start; t < end; ++t) {
        const int b = t >> 6, h0 = (t & 63) * 2;
        const unsigned char* xp = g_xTp + (size_t)b * 130 * 32768;
        const bool fresh = (t == start) || ((t & 63) == 0);
        const bool next_exists = (t + 1 < end);
        const bool next_fresh  = next_exists && (((t + 1) & 63) == 0);
        const int wait_stage = fresh ? 0 : 2;

#pragma unroll 1
        for (int s = 0; s < 6; ++s) {
            const int kh = s >> 1, cc = s & 1;

            if (s == wait_stage) { mbar_wait(sb + 8, (uint32_t)(xev & 1)); ++xev; }
            mbar_wait(sb + 24u + (uint32_t)((g & 1) << 3), (uint32_t)(g >> 1) & 1u);

            const uint32_t wbuf = sb + W_OFF + (uint32_t)((g & 1) ? 49152u : 0u);
            const uint32_t xb = sb + X_OFF
                              + (uint32_t)((((h0 + p + kh) & 3) * 2 + cc)) * 16384u;

#pragma unroll
            for (int kw = 0; kw < 3; ++kw) {
                const uint32_t wkw = wbuf + (uint32_t)kw * 16384u
                                   + (uint32_t)a_row * 128u;
                uint32_t rh[4], rx[4];
#pragma unroll
                for (int ntp = 0; ntp < 4; ++ntp) {
                    int r = b_n + ntp * 16 + kw - 1;
                    if ((unsigned)r > 127u) { rh[ntp] = zaddr; rx[ntp] = 0u; }
                    else { rh[ntp] = xb + (uint32_t)r * 128u; rx[ntp] = (uint32_t)((r & 7) << 4); }
                }
#pragma unroll
                for (int ks = 0; ks < 4; ++ks) {
                    const uint32_t koA = (uint32_t)(ks * 32) + a_kb;
                    const uint32_t koB = (uint32_t)(ks * 32) + b_kb;
                    uint32_t ah0[4], ah1[4], bh[16];
                    ldsm4(ah0, wkw + (koA ^ a_xor));
                    ldsm4(ah1, wkw + 2048u + (koA ^ a_xor));
#pragma unroll
                    for (int ntp = 0; ntp < 4; ++ntp)
                        ldsm4(&bh[ntp * 4], rh[ntp] + (koB ^ rx[ntp]));
#pragma unroll
                    for (int nt = 0; nt < 8; ++nt)
                        mma16816(C[nt], ah0, &bh[((nt >> 1) << 2) + ((nt & 1) << 1)]);
#pragma unroll
                    for (int nt = 0; nt < 8; ++nt)
                        mma16816(C[8 + nt], ah1, &bh[((nt >> 1) << 2) + ((nt & 1) << 1)]);
                }
            }

            __syncthreads();   // stage buffers fully consumed
            if (tid == 0) {
                if (g + 2 < nstages) {
                    uint32_t mb = sb + 24u + (uint32_t)((g & 1) << 3);
                    MBAR_EXPECT_TX(mb, 49152u);
                    bulk_g2s(sb + W_OFF + (uint32_t)((g & 1) ? 49152u : 0u),
                             g_Wp + (size_t)((g + 2) % 6) * 49152, 49152u, mb);
                }
                if (next_exists && !next_fresh && s == 3) {
                    // rows h0, h0+1 now dead; load next tile's rows h0+4, h0+5
                    MBAR_EXPECT_TX(sb + 8, 65536u);
#pragma unroll
                    for (int d = 4; d < 6; ++d)
#pragma unroll
                        for (int c2 = 0; c2 < 2; ++c2)
                            bulk_g2s(sb + X_OFF + (uint32_t)((((h0 + d) & 3) * 2 + c2)) * 16384u,
                                     xp + (size_t)((h0 + d) * 2 + c2) * 16384, 16384u, sb + 8);
                }
                if (next_fresh && s == 5) {
                    // full reload for column-crossing tile (h0'=0, new b)
                    int b1 = (t + 1) >> 6;
                    const unsigned char* xp1 = g_xTp + (size_t)b1 * 130 * 32768;
                    MBAR_EXPECT_TX(sb + 8, 131072u);
#pragma unroll
                    for (int d = 0; d < 4; ++d)
#pragma unroll
                        for (int c2 = 0; c2 < 2; ++c2)
                            bulk_g2s(sb + X_OFF + (uint32_t)(((d & 3) * 2 + c2)) * 16384u,
                                     xp1 + (size_t)(d * 2 + c2) * 16384, 16384u, sb + 8);
                }
            }
            ++g;
        }

        // ---- epilogue: direct register -> gmem, bias & stencil fused --------
        {
            const float* gdp = g_d + ((size_t)b << 14) + ((size_t)(h0 + p) << 7);
            float* ob = out + (size_t)b * IMG + ((size_t)(h0 + p) << 7);
#pragma unroll
            for (int s16 = 0; s16 < 2; ++s16) {
                const int r0 = row0 + s16 * 16;
                const float bv0 = p ? (s16 ? bv10 : bv00) : (s16 ? bv10 : bv00);
                const float bva = s16 ? bv10 : bv00;
                const float bvb = s16 ? bv11 : bv01;
                (void)bv0;
                float* o0 = ob + ((size_t)r0 << 14);
                float* o1 = ob + ((size_t)(r0 + 8) << 14);
#pragma unroll
                for (int nt = 0; nt < 8; ++nt) {
                    const int c = col0 + nt * 8;
                    const float g0 = __ldg(&gdp[c]), g1 = __ldg(&gdp[c + 1]);
                    float* Cp = C[s16 * 8 + nt];
                    *(float2*)&o0[c] = make_float2(Cp[0] + bva - g0, Cp[1] + bva - g1);
                    *(float2*)&o1[c] = make_float2(Cp[2] + bvb - g0, Cp[3] + bvb - g1);
                }
            }
#pragma unroll
            for (int nt = 0; nt < 16; ++nt)
#pragma unroll
                for (int i = 0; i < 4; ++i) C[nt][i] = 0.f;
        }
    }
}

// ---------------------------------------------------------------------------
extern "C" void kernel_launch(void* const* d_in, const int* in_sizes, int n_in,
                              void* d_out, int out_size) {
    const float* x  = (const float*)d_in[0];
    const float* Wt = (const float*)d_in[1];
    const float* bb = (const float*)d_in[2];
    float* out = (float*)d_out;
    (void)in_sizes; (void)n_in; (void)out_size;

    cudaFuncSetAttribute(k_prep_x, cudaFuncAttributeMaxDynamicSharedMemorySize, 49408);
    cudaFuncSetAttribute(k_main,   cudaFuncAttributeMaxDynamicSharedMemorySize, SMEM_TOTAL);

    k_prep_w<<<dim3(2, 3, 3), 256>>>(Wt);
    k_zero<<<512, 256>>>();
    k_prep_x<<<dim3(2, 128, 32), 256, 49408>>>(x);
    k_stencil<<<NB * HWSZ / 256, 256>>>();
    k_main<<<NCTA, 512, SMEM_TOTAL>>>(bb, out);
}